// round 1
// baseline (speedup 1.0000x reference)
#include <cuda_runtime.h>
#include <cuda_bf16.h>
#include <cstdint>

// ---------------- problem constants ----------------
#define Bv      4
#define Lv      2048
#define DIN     128
#define DM      256
#define NLAYERS 2
#define DI      512
#define DS      16
#define DCONV   4
#define DTR     16
#define ML      (Bv * Lv)          // 8192 rows
#define EPSV    1e-5f

// ---------------- scratch (static device memory; no allocs) ----------------
__device__ float g_h[ML * DM];           // residual stream
__device__ float g_u[ML * DM];           // rmsnorm output
__device__ float g_xz[ML * 2 * DI];      // in_proj output (x | z)
__device__ float g_xb[ML * DI];          // conv+silu output
__device__ float g_dbl[ML * 48];         // x_proj output (dt_rank | B | C)
__device__ float g_delta[ML * DI];       // softplus(dt)
__device__ float g_y[ML * DI];           // scan output (gated)

// ---------------- GEMM: C[M,N] = A[M,K] @ W[N,K]^T (+bias / +=residual) ----
// MODE 0: C = AW^T ; MODE 1: C = AW^T + bias ; MODE 2: C += AW^T
template <int MODE>
__global__ __launch_bounds__(256) void gemm_nt(
    const float* __restrict__ A, const float* __restrict__ W,
    const float* __restrict__ bias, float* __restrict__ C,
    int M, int N, int K)
{
    const int BM = 64, BN = 64, BK = 16;
    __shared__ float As[BK][BM + 4];
    __shared__ float Ws[BK][BN + 4];

    const int bm = blockIdx.y * BM;
    const int bn = blockIdx.x * BN;
    const int tid = threadIdx.x;
    const int tr = tid / 16;      // 0..15
    const int tc = tid % 16;      // 0..15

    float acc[4][4];
#pragma unroll
    for (int i = 0; i < 4; i++)
#pragma unroll
        for (int j = 0; j < 4; j++) acc[i][j] = 0.f;

    const int lr  = tid / 4;            // 0..63 row within tile
    const int lc4 = (tid % 4) * 4;      // 0,4,8,12 col within BK

    for (int k0 = 0; k0 < K; k0 += BK) {
        // load A tile (64 x 16)
        {
            float4 v = *(const float4*)&A[(size_t)(bm + lr) * K + k0 + lc4];
            As[lc4 + 0][lr] = v.x; As[lc4 + 1][lr] = v.y;
            As[lc4 + 2][lr] = v.z; As[lc4 + 3][lr] = v.w;
        }
        // load W tile (64 x 16) with N guard
        {
            float4 v = make_float4(0.f, 0.f, 0.f, 0.f);
            if (bn + lr < N)
                v = *(const float4*)&W[(size_t)(bn + lr) * K + k0 + lc4];
            Ws[lc4 + 0][lr] = v.x; Ws[lc4 + 1][lr] = v.y;
            Ws[lc4 + 2][lr] = v.z; Ws[lc4 + 3][lr] = v.w;
        }
        __syncthreads();

#pragma unroll
        for (int k = 0; k < BK; k++) {
            float a[4], w[4];
#pragma unroll
            for (int i = 0; i < 4; i++) a[i] = As[k][tr * 4 + i];
#pragma unroll
            for (int j = 0; j < 4; j++) w[j] = Ws[k][tc * 4 + j];
#pragma unroll
            for (int i = 0; i < 4; i++)
#pragma unroll
                for (int j = 0; j < 4; j++) acc[i][j] = fmaf(a[i], w[j], acc[i][j]);
        }
        __syncthreads();
    }

#pragma unroll
    for (int i = 0; i < 4; i++) {
        const size_t m = bm + tr * 4 + i;
#pragma unroll
        for (int j = 0; j < 4; j++) {
            const int n = bn + tc * 4 + j;
            if (n < N) {
                const size_t idx = m * (size_t)N + n;
                if (MODE == 2)      C[idx] += acc[i][j];
                else if (MODE == 1) C[idx] = acc[i][j] + bias[n];
                else                C[idx] = acc[i][j];
            }
        }
    }
}

// ---------------- rmsnorm over last dim (DM=256), one block per row --------
__global__ __launch_bounds__(256) void rmsnorm_kernel(
    const float* __restrict__ h, const float* __restrict__ w,
    float* __restrict__ u)
{
    const size_t row = blockIdx.x;
    const int t = threadIdx.x;
    const float v = h[row * DM + t];
    float ss = v * v;
    // warp reduce
#pragma unroll
    for (int o = 16; o > 0; o >>= 1) ss += __shfl_xor_sync(0xffffffffu, ss, o);
    __shared__ float sred[8];
    if ((t & 31) == 0) sred[t >> 5] = ss;
    __syncthreads();
    float tot = 0.f;
#pragma unroll
    for (int i = 0; i < 8; i++) tot += sred[i];
    const float scale = rsqrtf(tot * (1.f / DM) + EPSV);
    u[row * DM + t] = v * scale * w[t];
}

// ---------------- causal depthwise conv (width 4) + silu -------------------
__global__ __launch_bounds__(256) void conv_silu_kernel(
    const float* __restrict__ xz, const float* __restrict__ cw,
    const float* __restrict__ cb, float* __restrict__ xb)
{
    const int i = blockIdx.x * blockDim.x + threadIdx.x;
    if (i >= ML * DI) return;
    const int e = i % DI;
    const int l = (i / DI) % Lv;
    const int b = i / (DI * Lv);
    float acc = cb[e];
#pragma unroll
    for (int j = 0; j < DCONV; j++) {
        const int ls = l - (DCONV - 1) + j;
        if (ls >= 0)
            acc = fmaf(xz[((size_t)(b * Lv + ls)) * (2 * DI) + e], cw[e * DCONV + j], acc);
    }
    // silu
    const float s = acc / (1.f + __expf(-acc));
    xb[i] = s;
}

// ---------------- delta = softplus(dbl[:, :16] @ dt_w^T + dt_b) ------------
__global__ __launch_bounds__(512) void delta_kernel(
    const float* __restrict__ dbl, const float* __restrict__ dtw,
    const float* __restrict__ dtb, float* __restrict__ delta)
{
    const size_t row = blockIdx.x;
    const int e = threadIdx.x;
    __shared__ float s[DTR];
    if (e < DTR) s[e] = dbl[row * 48 + e];
    __syncthreads();
    float acc = dtb[e];
#pragma unroll
    for (int r = 0; r < DTR; r++) acc = fmaf(s[r], dtw[e * DTR + r], acc);
    // numerically stable softplus
    const float sp = fmaxf(acc, 0.f) + log1pf(__expf(-fabsf(acc)));
    delta[row * DI + e] = sp;
}

// ---------------- selective scan + gating -----------------------------------
// 16 lanes per channel (one per state), 2 channels per warp, 4 warps/block =
// 8 channels/block. Grid = Bv * (DI/8) = 256 blocks. 1-deep prefetch so the
// carried dependency is just the h-FMA chain.
__global__ __launch_bounds__(128) void scan_kernel(
    const float* __restrict__ delta, const float* __restrict__ u,
    const float* __restrict__ dbl,   const float* __restrict__ xz,
    const float* __restrict__ A_log, const float* __restrict__ Dp,
    float* __restrict__ y)
{
    const int warp = threadIdx.x >> 5;
    const int lane = threadIdx.x & 31;
    const int half = lane >> 4;            // which channel within warp
    const int n    = lane & 15;            // state index
    const int b    = blockIdx.x >> 6;      // batch
    const int chg  = blockIdx.x & 63;
    const int ch   = chg * 8 + warp * 2 + half;

    const float Aen = -__expf(A_log[ch * DS + n]);
    const float Dpe = Dp[ch];

    const size_t base = (size_t)b * Lv;

    float hstate = 0.f;
    // prefetch l = 0
    float dlt = delta[base * DI + ch];
    float uu  = u[base * DI + ch];
    float Bn  = dbl[base * 48 + DTR + n];
    float Cn  = dbl[base * 48 + DTR + DS + n];

    for (int l = 0; l < Lv; l++) {
        const float dlt_c = dlt, uu_c = uu, Bn_c = Bn, Cn_c = Cn;
        if (l + 1 < Lv) {
            const size_t r2 = base + l + 1;
            dlt = delta[r2 * DI + ch];
            uu  = u[r2 * DI + ch];
            Bn  = dbl[r2 * 48 + DTR + n];
            Cn  = dbl[r2 * 48 + DTR + DS + n];
        }
        const float dA = __expf(dlt_c * Aen);
        hstate = fmaf(dA, hstate, dlt_c * uu_c * Bn_c);
        float acc = hstate * Cn_c;
        acc += __shfl_xor_sync(0xffffffffu, acc, 1);
        acc += __shfl_xor_sync(0xffffffffu, acc, 2);
        acc += __shfl_xor_sync(0xffffffffu, acc, 4);
        acc += __shfl_xor_sync(0xffffffffu, acc, 8);
        if (n == 0) {
            const size_t row = base + l;
            const float zv = xz[row * (2 * DI) + DI + ch];
            const float sz = zv / (1.f + __expf(-zv));
            y[row * DI + ch] = (acc + uu_c * Dpe) * sz;
        }
    }
}

// ---------------- launch ----------------------------------------------------
extern "C" void kernel_launch(void* const* d_in, const int* in_sizes, int n_in,
                              void* d_out, int out_size)
{
    const float* x      = (const float*)d_in[0];   // (4,2048,128)
    const float* W1     = (const float*)d_in[1];   // (256,128)
    const float* b1     = (const float*)d_in[2];   // (256)
    const float* W2     = (const float*)d_in[3];   // (128,256)
    const float* b2     = (const float*)d_in[4];   // (128)
    const float* norm_w = (const float*)d_in[5];   // (2,256)
    const float* in_w   = (const float*)d_in[6];   // (2,1024,256)
    const float* conv_w = (const float*)d_in[7];   // (2,512,4)
    const float* conv_b = (const float*)d_in[8];   // (2,512)
    const float* xp_w   = (const float*)d_in[9];   // (2,48,512)
    const float* dt_w   = (const float*)d_in[10];  // (2,512,16)
    const float* dt_b   = (const float*)d_in[11];  // (2,512)
    const float* A_log  = (const float*)d_in[12];  // (2,512,16)
    const float* D_par  = (const float*)d_in[13];  // (2,512)
    const float* out_w  = (const float*)d_in[14];  // (2,256,512)
    float* out = (float*)d_out;                    // (4,2048,128)

    float *hbuf, *ubuf, *xzbuf, *xbbuf, *dblbuf, *deltabuf, *ybuf;
    cudaGetSymbolAddress((void**)&hbuf,     g_h);
    cudaGetSymbolAddress((void**)&ubuf,     g_u);
    cudaGetSymbolAddress((void**)&xzbuf,    g_xz);
    cudaGetSymbolAddress((void**)&xbbuf,    g_xb);
    cudaGetSymbolAddress((void**)&dblbuf,   g_dbl);
    cudaGetSymbolAddress((void**)&deltabuf, g_delta);
    cudaGetSymbolAddress((void**)&ybuf,     g_y);

    const dim3 blk(256);

    // h = x @ W1^T + b1       (M=8192, N=256, K=128)
    gemm_nt<1><<<dim3(DM / 64, ML / 64), blk>>>(x, W1, b1, hbuf, ML, DM, DIN);

    for (int l = 0; l < NLAYERS; l++) {
        const float* nw  = norm_w + (size_t)l * DM;
        const float* iw  = in_w   + (size_t)l * 2 * DI * DM;
        const float* cw  = conv_w + (size_t)l * DI * DCONV;
        const float* cb  = conv_b + (size_t)l * DI;
        const float* xpw = xp_w   + (size_t)l * 48 * DI;
        const float* dtw = dt_w   + (size_t)l * DI * DTR;
        const float* dtb = dt_b   + (size_t)l * DI;
        const float* Al  = A_log  + (size_t)l * DI * DS;
        const float* Dl  = D_par  + (size_t)l * DI;
        const float* ow  = out_w  + (size_t)l * DM * DI;

        // u = rmsnorm(h) * nw
        rmsnorm_kernel<<<ML, DM>>>(hbuf, nw, ubuf);
        // xz = u @ in_w^T      (N=1024, K=256)
        gemm_nt<0><<<dim3(2 * DI / 64, ML / 64), blk>>>(ubuf, iw, nullptr, xzbuf, ML, 2 * DI, DM);
        // xb = silu(conv(xz[:, :512]))
        conv_silu_kernel<<<(ML * DI + 255) / 256, blk>>>(xzbuf, cw, cb, xbbuf);
        // dbl = xb @ xp_w^T    (N=48, K=512)
        gemm_nt<0><<<dim3(1, ML / 64), blk>>>(xbbuf, xpw, nullptr, dblbuf, ML, 48, DI);
        // delta = softplus(dbl[:, :16] @ dt_w^T + dt_b)
        delta_kernel<<<ML, DI>>>(dblbuf, dtw, dtb, deltabuf);
        // y = gated selective scan
        scan_kernel<<<Bv * (DI / 8), 128>>>(deltabuf, xbbuf, dblbuf, xzbuf, Al, Dl, ybuf);
        // h += y @ out_w^T     (N=256, K=512)
        gemm_nt<2><<<dim3(DM / 64, ML / 64), blk>>>(ybuf, ow, nullptr, hbuf, ML, DM, DI);
    }

    // out = h @ W2^T + b2     (N=128, K=256)
    gemm_nt<1><<<dim3(DIN / 64, ML / 64), blk>>>(hbuf, W2, b2, out, ML, DIN, DM);
}

// round 2
// speedup vs baseline: 1.0231x; 1.0231x over previous
#include <cuda_runtime.h>
#include <cuda_bf16.h>
#include <cstdint>

// ---------------- problem constants ----------------
#define Bv      4
#define Lv      2048
#define DIN     128
#define DM      256
#define NLAYERS 2
#define DI      512
#define DS      16
#define DCONV   4
#define DTR     16
#define ML      (Bv * Lv)          // 8192 rows
#define EPSV    1e-5f

// ---------------- scratch (static device memory; no allocs) ----------------
__device__ float g_h[ML * DM];           // residual stream
__device__ float g_u[ML * DM];           // rmsnorm output
__device__ float g_xz[ML * 2 * DI];      // in_proj output (x | z)
__device__ float g_xb[ML * DI];          // conv+silu output
__device__ float g_dbl[ML * 48];         // x_proj output (dt_rank | B | C)
__device__ float g_delta[ML * DI];       // softplus(dt)
__device__ float g_y[ML * DI];           // scan output (gated)

// ============================================================================
// GEMM 128x128x8, 8x8/thread, double-buffered smem, register-staged prefetch.
// C[M,N] = A[M,K] @ W[N,K]^T.  MODE 0: C=; 1: C=+bias; 2: C+=.
// Requires: M%128==0, N%128==0, K%8==0, rows of A/W 16B-aligned.
// ============================================================================
template <int MODE>
__global__ __launch_bounds__(256, 2) void gemm128(
    const float* __restrict__ A, const float* __restrict__ W,
    const float* __restrict__ bias, float* __restrict__ C,
    int M, int N, int K)
{
    constexpr int BM = 128, BN = 128, BK = 8;
    __shared__ float As[2][BK][BM];
    __shared__ float Ws[2][BK][BN];

    const int bm = blockIdx.y * BM;
    const int bn = blockIdx.x * BN;
    const int tid = threadIdx.x;
    const int tx = tid & 15;        // 16 col-threads
    const int ty = tid >> 4;        // 16 row-threads

    // loader mapping: 128 threads per "column group" of 4 k's
    const int lr = tid & 127;            // row within tile
    const int lc = (tid >> 7) * 4;       // k offset: 0 or 4

    const float* aptr = A + (size_t)(bm + lr) * K + lc;
    const float* wptr = W + (size_t)(bn + lr) * K + lc;

    float acc[8][8];
#pragma unroll
    for (int i = 0; i < 8; i++)
#pragma unroll
        for (int j = 0; j < 8; j++) acc[i][j] = 0.f;

    // preload tile 0
    {
        float4 av = *(const float4*)aptr;
        float4 wv = *(const float4*)wptr;
        As[0][lc + 0][lr] = av.x; As[0][lc + 1][lr] = av.y;
        As[0][lc + 2][lr] = av.z; As[0][lc + 3][lr] = av.w;
        Ws[0][lc + 0][lr] = wv.x; Ws[0][lc + 1][lr] = wv.y;
        Ws[0][lc + 2][lr] = wv.z; Ws[0][lc + 3][lr] = wv.w;
    }
    __syncthreads();

    int cur = 0;
    for (int k0 = 0; k0 < K; k0 += BK) {
        float4 av, wv;
        const bool has_next = (k0 + BK) < K;
        if (has_next) {
            av = *(const float4*)(aptr + k0 + BK);
            wv = *(const float4*)(wptr + k0 + BK);
        }
#pragma unroll
        for (int k = 0; k < BK; k++) {
            float4 a0 = *(const float4*)&As[cur][k][ty * 8];
            float4 a1 = *(const float4*)&As[cur][k][ty * 8 + 4];
            float4 b0 = *(const float4*)&Ws[cur][k][tx * 8];
            float4 b1 = *(const float4*)&Ws[cur][k][tx * 8 + 4];
            float a[8] = {a0.x, a0.y, a0.z, a0.w, a1.x, a1.y, a1.z, a1.w};
            float b[8] = {b0.x, b0.y, b0.z, b0.w, b1.x, b1.y, b1.z, b1.w};
#pragma unroll
            for (int i = 0; i < 8; i++)
#pragma unroll
                for (int j = 0; j < 8; j++)
                    acc[i][j] = fmaf(a[i], b[j], acc[i][j]);
        }
        if (has_next) {
            const int nb = cur ^ 1;
            As[nb][lc + 0][lr] = av.x; As[nb][lc + 1][lr] = av.y;
            As[nb][lc + 2][lr] = av.z; As[nb][lc + 3][lr] = av.w;
            Ws[nb][lc + 0][lr] = wv.x; Ws[nb][lc + 1][lr] = wv.y;
            Ws[nb][lc + 2][lr] = wv.z; Ws[nb][lc + 3][lr] = wv.w;
        }
        __syncthreads();
        cur ^= 1;
    }

    // epilogue
#pragma unroll
    for (int i = 0; i < 8; i++) {
        const size_t m = bm + ty * 8 + i;
        float* crow = C + m * (size_t)N + bn + tx * 8;
#pragma unroll
        for (int j2 = 0; j2 < 8; j2 += 4) {
            float4 v = make_float4(acc[i][j2], acc[i][j2 + 1], acc[i][j2 + 2], acc[i][j2 + 3]);
            if (MODE == 1) {
                float4 bb = *(const float4*)&bias[bn + tx * 8 + j2];
                v.x += bb.x; v.y += bb.y; v.z += bb.z; v.w += bb.w;
            } else if (MODE == 2) {
                float4 o = *(const float4*)(crow + j2);
                v.x += o.x; v.y += o.y; v.z += o.z; v.w += o.w;
            }
            *(float4*)(crow + j2) = v;
        }
    }
}

// ============================================================================
// GEMM 128x64x8, 8x4/thread variant, with optional N guard (for N=48, N=128).
// ============================================================================
template <int MODE, bool NGUARD>
__global__ __launch_bounds__(256, 2) void gemm64(
    const float* __restrict__ A, const float* __restrict__ W,
    const float* __restrict__ bias, float* __restrict__ C,
    int M, int N, int K)
{
    constexpr int BM = 128, BN = 64, BK = 8;
    __shared__ float As[2][BK][BM];
    __shared__ float Ws[2][BK][BN];

    const int bm = blockIdx.y * BM;
    const int bn = blockIdx.x * BN;
    const int tid = threadIdx.x;
    const int tx = tid & 15;
    const int ty = tid >> 4;

    const int lr  = tid & 127;
    const int lc  = (tid >> 7) * 4;
    const int wr  = tid & 63;
    const int wc  = (tid >> 6) * 2;

    const float* aptr = A + (size_t)(bm + lr) * K + lc;
    const bool wvalid = !NGUARD || (bn + wr) < N;
    const float* wptr = W + (size_t)(bn + (wvalid ? wr : 0)) * K + wc;

    float acc[8][4];
#pragma unroll
    for (int i = 0; i < 8; i++)
#pragma unroll
        for (int j = 0; j < 4; j++) acc[i][j] = 0.f;

    {
        float4 av = *(const float4*)aptr;
        float2 wv = wvalid ? *(const float2*)wptr : make_float2(0.f, 0.f);
        As[0][lc + 0][lr] = av.x; As[0][lc + 1][lr] = av.y;
        As[0][lc + 2][lr] = av.z; As[0][lc + 3][lr] = av.w;
        Ws[0][wc + 0][wr] = wv.x; Ws[0][wc + 1][wr] = wv.y;
    }
    __syncthreads();

    int cur = 0;
    for (int k0 = 0; k0 < K; k0 += BK) {
        float4 av; float2 wv;
        const bool has_next = (k0 + BK) < K;
        if (has_next) {
            av = *(const float4*)(aptr + k0 + BK);
            wv = wvalid ? *(const float2*)(wptr + k0 + BK) : make_float2(0.f, 0.f);
        }
#pragma unroll
        for (int k = 0; k < BK; k++) {
            float4 a0 = *(const float4*)&As[cur][k][ty * 8];
            float4 a1 = *(const float4*)&As[cur][k][ty * 8 + 4];
            float4 b0 = *(const float4*)&Ws[cur][k][tx * 4];
            float a[8] = {a0.x, a0.y, a0.z, a0.w, a1.x, a1.y, a1.z, a1.w};
            float b[4] = {b0.x, b0.y, b0.z, b0.w};
#pragma unroll
            for (int i = 0; i < 8; i++)
#pragma unroll
                for (int j = 0; j < 4; j++)
                    acc[i][j] = fmaf(a[i], b[j], acc[i][j]);
        }
        if (has_next) {
            const int nb = cur ^ 1;
            As[nb][lc + 0][lr] = av.x; As[nb][lc + 1][lr] = av.y;
            As[nb][lc + 2][lr] = av.z; As[nb][lc + 3][lr] = av.w;
            Ws[nb][wc + 0][wr] = wv.x; Ws[nb][wc + 1][wr] = wv.y;
        }
        __syncthreads();
        cur ^= 1;
    }

#pragma unroll
    for (int i = 0; i < 8; i++) {
        const size_t m = bm + ty * 8 + i;
        const int col = bn + tx * 4;
        if (NGUARD && col >= N) continue;
        float* crow = C + m * (size_t)N + col;
        float4 v = make_float4(acc[i][0], acc[i][1], acc[i][2], acc[i][3]);
        if (MODE == 1) {
            float4 bb = *(const float4*)&bias[col];
            v.x += bb.x; v.y += bb.y; v.z += bb.z; v.w += bb.w;
        } else if (MODE == 2) {
            float4 o = *(const float4*)crow;
            v.x += o.x; v.y += o.y; v.z += o.z; v.w += o.w;
        }
        *(float4*)crow = v;
    }
}

// ---------------- rmsnorm over last dim (DM=256), one block per row --------
__global__ __launch_bounds__(256) void rmsnorm_kernel(
    const float* __restrict__ h, const float* __restrict__ w,
    float* __restrict__ u)
{
    const size_t row = blockIdx.x;
    const int t = threadIdx.x;
    const float v = h[row * DM + t];
    float ss = v * v;
#pragma unroll
    for (int o = 16; o > 0; o >>= 1) ss += __shfl_xor_sync(0xffffffffu, ss, o);
    __shared__ float sred[8];
    if ((t & 31) == 0) sred[t >> 5] = ss;
    __syncthreads();
    float tot = 0.f;
#pragma unroll
    for (int i = 0; i < 8; i++) tot += sred[i];
    const float scale = rsqrtf(tot * (1.f / DM) + EPSV);
    u[row * DM + t] = v * scale * w[t];
}

// ---------------- causal depthwise conv (width 4) + silu -------------------
__global__ __launch_bounds__(256) void conv_silu_kernel(
    const float* __restrict__ xz, const float* __restrict__ cw,
    const float* __restrict__ cb, float* __restrict__ xb)
{
    const int i = blockIdx.x * blockDim.x + threadIdx.x;
    if (i >= ML * DI) return;
    const int e = i % DI;
    const int l = (i / DI) % Lv;
    const int b = i / (DI * Lv);
    float acc = cb[e];
#pragma unroll
    for (int j = 0; j < DCONV; j++) {
        const int ls = l - (DCONV - 1) + j;
        if (ls >= 0)
            acc = fmaf(xz[((size_t)(b * Lv + ls)) * (2 * DI) + e], cw[e * DCONV + j], acc);
    }
    const float s = acc / (1.f + __expf(-acc));
    xb[i] = s;
}

// ---------------- delta = softplus(dbl[:, :16] @ dt_w^T + dt_b) ------------
__global__ __launch_bounds__(512) void delta_kernel(
    const float* __restrict__ dbl, const float* __restrict__ dtw,
    const float* __restrict__ dtb, float* __restrict__ delta)
{
    const size_t row = blockIdx.x;
    const int e = threadIdx.x;
    __shared__ float s[DTR];
    if (e < DTR) s[e] = dbl[row * 48 + e];
    __syncthreads();
    float acc = dtb[e];
#pragma unroll
    for (int r = 0; r < DTR; r++) acc = fmaf(s[r], dtw[e * DTR + r], acc);
    const float sp = fmaxf(acc, 0.f) + log1pf(__expf(-fabsf(acc)));
    delta[row * DI + e] = sp;
}

// ---------------- selective scan + gating ----------------------------------
__global__ __launch_bounds__(128) void scan_kernel(
    const float* __restrict__ delta, const float* __restrict__ u,
    const float* __restrict__ dbl,   const float* __restrict__ xz,
    const float* __restrict__ A_log, const float* __restrict__ Dp,
    float* __restrict__ y)
{
    const int warp = threadIdx.x >> 5;
    const int lane = threadIdx.x & 31;
    const int half = lane >> 4;
    const int n    = lane & 15;
    const int b    = blockIdx.x >> 6;
    const int chg  = blockIdx.x & 63;
    const int ch   = chg * 8 + warp * 2 + half;

    const float Aen = -__expf(A_log[ch * DS + n]);
    const float Dpe = Dp[ch];

    const size_t base = (size_t)b * Lv;

    float hstate = 0.f;
    float dlt = delta[base * DI + ch];
    float uu  = u[base * DI + ch];
    float Bn  = dbl[base * 48 + DTR + n];
    float Cn  = dbl[base * 48 + DTR + DS + n];

    for (int l = 0; l < Lv; l++) {
        const float dlt_c = dlt, uu_c = uu, Bn_c = Bn, Cn_c = Cn;
        if (l + 1 < Lv) {
            const size_t r2 = base + l + 1;
            dlt = delta[r2 * DI + ch];
            uu  = u[r2 * DI + ch];
            Bn  = dbl[r2 * 48 + DTR + n];
            Cn  = dbl[r2 * 48 + DTR + DS + n];
        }
        const float dA = __expf(dlt_c * Aen);
        hstate = fmaf(dA, hstate, dlt_c * uu_c * Bn_c);
        float acc = hstate * Cn_c;
        acc += __shfl_xor_sync(0xffffffffu, acc, 1);
        acc += __shfl_xor_sync(0xffffffffu, acc, 2);
        acc += __shfl_xor_sync(0xffffffffu, acc, 4);
        acc += __shfl_xor_sync(0xffffffffu, acc, 8);
        if (n == 0) {
            const size_t row = base + l;
            const float zv = xz[row * (2 * DI) + DI + ch];
            const float sz = zv / (1.f + __expf(-zv));
            y[row * DI + ch] = (acc + uu_c * Dpe) * sz;
        }
    }
}

// ---------------- launch ----------------------------------------------------
extern "C" void kernel_launch(void* const* d_in, const int* in_sizes, int n_in,
                              void* d_out, int out_size)
{
    const float* x      = (const float*)d_in[0];
    const float* W1     = (const float*)d_in[1];
    const float* b1     = (const float*)d_in[2];
    const float* W2     = (const float*)d_in[3];
    const float* b2     = (const float*)d_in[4];
    const float* norm_w = (const float*)d_in[5];
    const float* in_w   = (const float*)d_in[6];
    const float* conv_w = (const float*)d_in[7];
    const float* conv_b = (const float*)d_in[8];
    const float* xp_w   = (const float*)d_in[9];
    const float* dt_w   = (const float*)d_in[10];
    const float* dt_b   = (const float*)d_in[11];
    const float* A_log  = (const float*)d_in[12];
    const float* D_par  = (const float*)d_in[13];
    const float* out_w  = (const float*)d_in[14];
    float* out = (float*)d_out;

    float *hbuf, *ubuf, *xzbuf, *xbbuf, *dblbuf, *deltabuf, *ybuf;
    cudaGetSymbolAddress((void**)&hbuf,     g_h);
    cudaGetSymbolAddress((void**)&ubuf,     g_u);
    cudaGetSymbolAddress((void**)&xzbuf,    g_xz);
    cudaGetSymbolAddress((void**)&xbbuf,    g_xb);
    cudaGetSymbolAddress((void**)&dblbuf,   g_dbl);
    cudaGetSymbolAddress((void**)&deltabuf, g_delta);
    cudaGetSymbolAddress((void**)&ybuf,     g_y);

    const dim3 blk(256);

    // h = x @ W1^T + b1       (M=8192, N=256, K=128)
    gemm128<1><<<dim3(DM / 128, ML / 128), blk>>>(x, W1, b1, hbuf, ML, DM, DIN);

    for (int l = 0; l < NLAYERS; l++) {
        const float* nw  = norm_w + (size_t)l * DM;
        const float* iw  = in_w   + (size_t)l * 2 * DI * DM;
        const float* cw  = conv_w + (size_t)l * DI * DCONV;
        const float* cb  = conv_b + (size_t)l * DI;
        const float* xpw = xp_w   + (size_t)l * 48 * DI;
        const float* dtw = dt_w   + (size_t)l * DI * DTR;
        const float* dtb = dt_b   + (size_t)l * DI;
        const float* Al  = A_log  + (size_t)l * DI * DS;
        const float* Dl  = D_par  + (size_t)l * DI;
        const float* ow  = out_w  + (size_t)l * DM * DI;

        // u = rmsnorm(h) * nw
        rmsnorm_kernel<<<ML, DM>>>(hbuf, nw, ubuf);
        // xz = u @ in_w^T      (N=1024, K=256)
        gemm128<0><<<dim3(2 * DI / 128, ML / 128), blk>>>(ubuf, iw, nullptr, xzbuf, ML, 2 * DI, DM);
        // xb = silu(conv(xz[:, :512]))
        conv_silu_kernel<<<(ML * DI + 255) / 256, blk>>>(xzbuf, cw, cb, xbbuf);
        // dbl = xb @ xp_w^T    (N=48, K=512)
        gemm64<0, true><<<dim3(1, ML / 128), blk>>>(xbbuf, xpw, nullptr, dblbuf, ML, 48, DI);
        // delta = softplus(dbl[:, :16] @ dt_w^T + dt_b)
        delta_kernel<<<ML, DI>>>(dblbuf, dtw, dtb, deltabuf);
        // y = gated selective scan
        scan_kernel<<<Bv * (DI / 8), 128>>>(deltabuf, xbbuf, dblbuf, xzbuf, Al, Dl, ybuf);
        // h += y @ out_w^T     (N=256, K=512)
        gemm128<2><<<dim3(DM / 128, ML / 128), blk>>>(ybuf, ow, nullptr, hbuf, ML, DM, DI);
    }

    // out = h @ W2^T + b2     (N=128, K=256)
    gemm64<1, false><<<dim3(DIN / 64, ML / 128), blk>>>(hbuf, W2, b2, out, ML, DIN, DM);
}

// round 3
// speedup vs baseline: 2.6364x; 2.5769x over previous
#include <cuda_runtime.h>
#include <cuda_bf16.h>
#include <cstdint>

// ---------------- problem constants ----------------
#define Bv      4
#define Lv      2048
#define DIN     128
#define DM      256
#define NLAYERS 2
#define DI      512
#define DS      16
#define DCONV   4
#define DTR     16
#define ML      (Bv * Lv)          // 8192 rows
#define EPSV    1e-5f

// ---------------- scratch (static device memory; no allocs) ----------------
__device__ float g_h[ML * DM];           // residual stream
__device__ float g_u[ML * DM];           // rmsnorm output
__device__ float g_xz[ML * 2 * DI];      // in_proj output (x | z)
__device__ float g_xb[ML * DI];          // conv+silu output
__device__ float g_dbl[ML * 48];         // x_proj output (dt_rank | B | C)
__device__ float g_delta[ML * DI];       // softplus(dt)
__device__ float g_y[ML * DI];           // scan output (gated)

// ============================================================================
// GEMM 128x128x8, 8x8/thread, double-buffered smem, register-staged prefetch.
// ============================================================================
template <int MODE>
__global__ __launch_bounds__(256, 2) void gemm128(
    const float* __restrict__ A, const float* __restrict__ W,
    const float* __restrict__ bias, float* __restrict__ C,
    int M, int N, int K)
{
    constexpr int BM = 128, BN = 128, BK = 8;
    __shared__ float As[2][BK][BM];
    __shared__ float Ws[2][BK][BN];

    const int bm = blockIdx.y * BM;
    const int bn = blockIdx.x * BN;
    const int tid = threadIdx.x;
    const int tx = tid & 15;
    const int ty = tid >> 4;

    const int lr = tid & 127;
    const int lc = (tid >> 7) * 4;

    const float* aptr = A + (size_t)(bm + lr) * K + lc;
    const float* wptr = W + (size_t)(bn + lr) * K + lc;

    float acc[8][8];
#pragma unroll
    for (int i = 0; i < 8; i++)
#pragma unroll
        for (int j = 0; j < 8; j++) acc[i][j] = 0.f;

    {
        float4 av = *(const float4*)aptr;
        float4 wv = *(const float4*)wptr;
        As[0][lc + 0][lr] = av.x; As[0][lc + 1][lr] = av.y;
        As[0][lc + 2][lr] = av.z; As[0][lc + 3][lr] = av.w;
        Ws[0][lc + 0][lr] = wv.x; Ws[0][lc + 1][lr] = wv.y;
        Ws[0][lc + 2][lr] = wv.z; Ws[0][lc + 3][lr] = wv.w;
    }
    __syncthreads();

    int cur = 0;
    for (int k0 = 0; k0 < K; k0 += BK) {
        float4 av, wv;
        const bool has_next = (k0 + BK) < K;
        if (has_next) {
            av = *(const float4*)(aptr + k0 + BK);
            wv = *(const float4*)(wptr + k0 + BK);
        }
#pragma unroll
        for (int k = 0; k < BK; k++) {
            float4 a0 = *(const float4*)&As[cur][k][ty * 8];
            float4 a1 = *(const float4*)&As[cur][k][ty * 8 + 4];
            float4 b0 = *(const float4*)&Ws[cur][k][tx * 8];
            float4 b1 = *(const float4*)&Ws[cur][k][tx * 8 + 4];
            float a[8] = {a0.x, a0.y, a0.z, a0.w, a1.x, a1.y, a1.z, a1.w};
            float b[8] = {b0.x, b0.y, b0.z, b0.w, b1.x, b1.y, b1.z, b1.w};
#pragma unroll
            for (int i = 0; i < 8; i++)
#pragma unroll
                for (int j = 0; j < 8; j++)
                    acc[i][j] = fmaf(a[i], b[j], acc[i][j]);
        }
        if (has_next) {
            const int nb = cur ^ 1;
            As[nb][lc + 0][lr] = av.x; As[nb][lc + 1][lr] = av.y;
            As[nb][lc + 2][lr] = av.z; As[nb][lc + 3][lr] = av.w;
            Ws[nb][lc + 0][lr] = wv.x; Ws[nb][lc + 1][lr] = wv.y;
            Ws[nb][lc + 2][lr] = wv.z; Ws[nb][lc + 3][lr] = wv.w;
        }
        __syncthreads();
        cur ^= 1;
    }

#pragma unroll
    for (int i = 0; i < 8; i++) {
        const size_t m = bm + ty * 8 + i;
        float* crow = C + m * (size_t)N + bn + tx * 8;
#pragma unroll
        for (int j2 = 0; j2 < 8; j2 += 4) {
            float4 v = make_float4(acc[i][j2], acc[i][j2 + 1], acc[i][j2 + 2], acc[i][j2 + 3]);
            if (MODE == 1) {
                float4 bb = *(const float4*)&bias[bn + tx * 8 + j2];
                v.x += bb.x; v.y += bb.y; v.z += bb.z; v.w += bb.w;
            } else if (MODE == 2) {
                float4 o = *(const float4*)(crow + j2);
                v.x += o.x; v.y += o.y; v.z += o.z; v.w += o.w;
            }
            *(float4*)(crow + j2) = v;
        }
    }
}

// ============================================================================
// GEMM 128x64x8, 8x4/thread variant, with optional N guard (for N=48, N=128).
// ============================================================================
template <int MODE, bool NGUARD>
__global__ __launch_bounds__(256, 2) void gemm64(
    const float* __restrict__ A, const float* __restrict__ W,
    const float* __restrict__ bias, float* __restrict__ C,
    int M, int N, int K)
{
    constexpr int BM = 128, BN = 64, BK = 8;
    __shared__ float As[2][BK][BM];
    __shared__ float Ws[2][BK][BN];

    const int bm = blockIdx.y * BM;
    const int bn = blockIdx.x * BN;
    const int tid = threadIdx.x;
    const int tx = tid & 15;
    const int ty = tid >> 4;

    const int lr  = tid & 127;
    const int lc  = (tid >> 7) * 4;
    const int wr  = tid & 63;
    const int wc  = (tid >> 6) * 2;

    const float* aptr = A + (size_t)(bm + lr) * K + lc;
    const bool wvalid = !NGUARD || (bn + wr) < N;
    const float* wptr = W + (size_t)(bn + (wvalid ? wr : 0)) * K + wc;

    float acc[8][4];
#pragma unroll
    for (int i = 0; i < 8; i++)
#pragma unroll
        for (int j = 0; j < 4; j++) acc[i][j] = 0.f;

    {
        float4 av = *(const float4*)aptr;
        float2 wv = wvalid ? *(const float2*)wptr : make_float2(0.f, 0.f);
        As[0][lc + 0][lr] = av.x; As[0][lc + 1][lr] = av.y;
        As[0][lc + 2][lr] = av.z; As[0][lc + 3][lr] = av.w;
        Ws[0][wc + 0][wr] = wv.x; Ws[0][wc + 1][wr] = wv.y;
    }
    __syncthreads();

    int cur = 0;
    for (int k0 = 0; k0 < K; k0 += BK) {
        float4 av; float2 wv;
        const bool has_next = (k0 + BK) < K;
        if (has_next) {
            av = *(const float4*)(aptr + k0 + BK);
            wv = wvalid ? *(const float2*)(wptr + k0 + BK) : make_float2(0.f, 0.f);
        }
#pragma unroll
        for (int k = 0; k < BK; k++) {
            float4 a0 = *(const float4*)&As[cur][k][ty * 8];
            float4 a1 = *(const float4*)&As[cur][k][ty * 8 + 4];
            float4 b0 = *(const float4*)&Ws[cur][k][tx * 4];
            float a[8] = {a0.x, a0.y, a0.z, a0.w, a1.x, a1.y, a1.z, a1.w};
            float b[4] = {b0.x, b0.y, b0.z, b0.w};
#pragma unroll
            for (int i = 0; i < 8; i++)
#pragma unroll
                for (int j = 0; j < 4; j++)
                    acc[i][j] = fmaf(a[i], b[j], acc[i][j]);
        }
        if (has_next) {
            const int nb = cur ^ 1;
            As[nb][lc + 0][lr] = av.x; As[nb][lc + 1][lr] = av.y;
            As[nb][lc + 2][lr] = av.z; As[nb][lc + 3][lr] = av.w;
            Ws[nb][wc + 0][wr] = wv.x; Ws[nb][wc + 1][wr] = wv.y;
        }
        __syncthreads();
        cur ^= 1;
    }

#pragma unroll
    for (int i = 0; i < 8; i++) {
        const size_t m = bm + ty * 8 + i;
        const int col = bn + tx * 4;
        if (NGUARD && col >= N) continue;
        float* crow = C + m * (size_t)N + col;
        float4 v = make_float4(acc[i][0], acc[i][1], acc[i][2], acc[i][3]);
        if (MODE == 1) {
            float4 bb = *(const float4*)&bias[col];
            v.x += bb.x; v.y += bb.y; v.z += bb.z; v.w += bb.w;
        } else if (MODE == 2) {
            float4 o = *(const float4*)crow;
            v.x += o.x; v.y += o.y; v.z += o.z; v.w += o.w;
        }
        *(float4*)crow = v;
    }
}

// ---------------- rmsnorm over last dim (DM=256), one block per row --------
__global__ __launch_bounds__(256) void rmsnorm_kernel(
    const float* __restrict__ h, const float* __restrict__ w,
    float* __restrict__ u)
{
    const size_t row = blockIdx.x;
    const int t = threadIdx.x;
    const float v = h[row * DM + t];
    float ss = v * v;
#pragma unroll
    for (int o = 16; o > 0; o >>= 1) ss += __shfl_xor_sync(0xffffffffu, ss, o);
    __shared__ float sred[8];
    if ((t & 31) == 0) sred[t >> 5] = ss;
    __syncthreads();
    float tot = 0.f;
#pragma unroll
    for (int i = 0; i < 8; i++) tot += sred[i];
    const float scale = rsqrtf(tot * (1.f / DM) + EPSV);
    u[row * DM + t] = v * scale * w[t];
}

// ---------------- causal depthwise conv (width 4) + silu -------------------
__global__ __launch_bounds__(256) void conv_silu_kernel(
    const float* __restrict__ xz, const float* __restrict__ cw,
    const float* __restrict__ cb, float* __restrict__ xb)
{
    const int i = blockIdx.x * blockDim.x + threadIdx.x;
    if (i >= ML * DI) return;
    const int e = i % DI;
    const int l = (i / DI) % Lv;
    const int b = i / (DI * Lv);
    float acc = cb[e];
#pragma unroll
    for (int j = 0; j < DCONV; j++) {
        const int ls = l - (DCONV - 1) + j;
        if (ls >= 0)
            acc = fmaf(xz[((size_t)(b * Lv + ls)) * (2 * DI) + e], cw[e * DCONV + j], acc);
    }
    const float s = acc / (1.f + __expf(-acc));
    xb[i] = s;
}

// ---------------- delta = softplus(dbl[:, :16] @ dt_w^T + dt_b) ------------
__global__ __launch_bounds__(512) void delta_kernel(
    const float* __restrict__ dbl, const float* __restrict__ dtw,
    const float* __restrict__ dtb, float* __restrict__ delta)
{
    const size_t row = blockIdx.x;
    const int e = threadIdx.x;
    __shared__ float s[DTR];
    if (e < DTR) s[e] = dbl[row * 48 + e];
    __syncthreads();
    float acc = dtb[e];
#pragma unroll
    for (int r = 0; r < DTR; r++) acc = fmaf(s[r], dtw[e * DTR + r], acc);
    const float sp = fmaxf(acc, 0.f) + log1pf(__expf(-fabsf(acc)));
    delta[row * DI + e] = sp;
}

// ============================================================================
// Selective scan v2: chunked double-buffered smem staging.
// Block = 256 threads = 8 warps, 16 channels (2 per warp). Grid = 4*32 = 128.
// Per chunk of 64 timesteps, all inputs are cooperatively loaded (coalesced)
// into registers then staged to smem; the serial recurrence runs from smem.
// silu(z) is precomputed data-parallel during staging.
// ============================================================================
#define SCH    16
#define CHUNK  64
#define NCHUNK (Lv / CHUNK)

__global__ __launch_bounds__(256) void scan_kernel(
    const float* __restrict__ delta, const float* __restrict__ u,
    const float* __restrict__ dbl,   const float* __restrict__ xz,
    const float* __restrict__ A_log, const float* __restrict__ Dp,
    float* __restrict__ y)
{
    __shared__ float s_dlt[2][CHUNK][SCH];
    __shared__ float s_uu [2][CHUNK][SCH];
    __shared__ float s_sz [2][CHUNK][SCH];
    __shared__ float s_B  [2][CHUNK][SCH];
    __shared__ float s_C  [2][CHUNK][SCH];

    const int tid  = threadIdx.x;
    const int warp = tid >> 5;
    const int lane = tid & 31;
    const int half = lane >> 4;
    const int n    = lane & 15;
    const int cl   = warp * 2 + half;            // channel-local 0..15
    const int b      = (int)(blockIdx.x >> 5);   // 32 channel-groups per batch
    const int chbase = (blockIdx.x & 31) * SCH;
    const int ch     = chbase + cl;

    const float Aen = -__expf(A_log[ch * DS + n]);
    const float Dpe = Dp[ch];
    const size_t base = (size_t)b * Lv;

    // staging registers: 4 slabs of 16 timesteps each (tid -> (rr, cc))
    const int rr = tid >> 4;   // timestep within 16-row slab
    const int cc = tid & 15;   // channel / state index
    float r_d[4], r_u[4], r_z[4], r_b[4], r_c[4];

    auto LOADC = [&](int l0) {
#pragma unroll
        for (int i = 0; i < 4; i++) {
            const size_t row = base + l0 + rr + i * 16;
            r_d[i] = delta[row * DI + chbase + cc];
            r_u[i] = u[row * DI + chbase + cc];
            r_z[i] = xz[row * (size_t)(2 * DI) + DI + chbase + cc];
            r_b[i] = dbl[row * 48 + DTR + cc];
            r_c[i] = dbl[row * 48 + DTR + DS + cc];
        }
    };
    auto STORES = [&](int bf) {
#pragma unroll
        for (int i = 0; i < 4; i++) {
            const int t = rr + i * 16;
            s_dlt[bf][t][cc] = r_d[i];
            s_uu [bf][t][cc] = r_u[i];
            const float zz = r_z[i];
            s_sz [bf][t][cc] = zz / (1.f + __expf(-zz));
            s_B  [bf][t][cc] = r_b[i];
            s_C  [bf][t][cc] = r_c[i];
        }
    };

    LOADC(0);
    STORES(0);
    __syncthreads();

    float hst = 0.f;
    int buf = 0;
    for (int c = 0; c < NCHUNK; c++) {
        if (c + 1 < NCHUNK) LOADC((c + 1) * CHUNK);   // LDGs in flight over compute
        const int l0 = c * CHUNK;
#pragma unroll 4
        for (int t = 0; t < CHUNK; t++) {
            const float dlt = s_dlt[buf][t][cl];
            const float uu  = s_uu [buf][t][cl];
            const float Bn  = s_B  [buf][t][n];
            const float Cn  = s_C  [buf][t][n];
            const float dA  = __expf(dlt * Aen);
            hst = fmaf(dA, hst, dlt * uu * Bn);
            float acc = hst * Cn;
            acc += __shfl_xor_sync(0xffffffffu, acc, 1);
            acc += __shfl_xor_sync(0xffffffffu, acc, 2);
            acc += __shfl_xor_sync(0xffffffffu, acc, 4);
            acc += __shfl_xor_sync(0xffffffffu, acc, 8);
            if (n == 0) {
                y[(base + l0 + t) * DI + ch] = (acc + uu * Dpe) * s_sz[buf][t][cl];
            }
        }
        if (c + 1 < NCHUNK) STORES(buf ^ 1);
        __syncthreads();
        buf ^= 1;
    }
}

// ---------------- launch ----------------------------------------------------
extern "C" void kernel_launch(void* const* d_in, const int* in_sizes, int n_in,
                              void* d_out, int out_size)
{
    const float* x      = (const float*)d_in[0];
    const float* W1     = (const float*)d_in[1];
    const float* b1     = (const float*)d_in[2];
    const float* W2     = (const float*)d_in[3];
    const float* b2     = (const float*)d_in[4];
    const float* norm_w = (const float*)d_in[5];
    const float* in_w   = (const float*)d_in[6];
    const float* conv_w = (const float*)d_in[7];
    const float* conv_b = (const float*)d_in[8];
    const float* xp_w   = (const float*)d_in[9];
    const float* dt_w   = (const float*)d_in[10];
    const float* dt_b   = (const float*)d_in[11];
    const float* A_log  = (const float*)d_in[12];
    const float* D_par  = (const float*)d_in[13];
    const float* out_w  = (const float*)d_in[14];
    float* out = (float*)d_out;

    float *hbuf, *ubuf, *xzbuf, *xbbuf, *dblbuf, *deltabuf, *ybuf;
    cudaGetSymbolAddress((void**)&hbuf,     g_h);
    cudaGetSymbolAddress((void**)&ubuf,     g_u);
    cudaGetSymbolAddress((void**)&xzbuf,    g_xz);
    cudaGetSymbolAddress((void**)&xbbuf,    g_xb);
    cudaGetSymbolAddress((void**)&dblbuf,   g_dbl);
    cudaGetSymbolAddress((void**)&deltabuf, g_delta);
    cudaGetSymbolAddress((void**)&ybuf,     g_y);

    const dim3 blk(256);

    // h = x @ W1^T + b1       (M=8192, N=256, K=128)
    gemm128<1><<<dim3(DM / 128, ML / 128), blk>>>(x, W1, b1, hbuf, ML, DM, DIN);

    for (int l = 0; l < NLAYERS; l++) {
        const float* nw  = norm_w + (size_t)l * DM;
        const float* iw  = in_w   + (size_t)l * 2 * DI * DM;
        const float* cw  = conv_w + (size_t)l * DI * DCONV;
        const float* cb  = conv_b + (size_t)l * DI;
        const float* xpw = xp_w   + (size_t)l * 48 * DI;
        const float* dtw = dt_w   + (size_t)l * DI * DTR;
        const float* dtb = dt_b   + (size_t)l * DI;
        const float* Al  = A_log  + (size_t)l * DI * DS;
        const float* Dl  = D_par  + (size_t)l * DI;
        const float* ow  = out_w  + (size_t)l * DM * DI;

        rmsnorm_kernel<<<ML, DM>>>(hbuf, nw, ubuf);
        gemm128<0><<<dim3(2 * DI / 128, ML / 128), blk>>>(ubuf, iw, nullptr, xzbuf, ML, 2 * DI, DM);
        conv_silu_kernel<<<(ML * DI + 255) / 256, blk>>>(xzbuf, cw, cb, xbbuf);
        gemm64<0, true><<<dim3(1, ML / 128), blk>>>(xbbuf, xpw, nullptr, dblbuf, ML, 48, DI);
        delta_kernel<<<ML, DI>>>(dblbuf, dtw, dtb, deltabuf);
        scan_kernel<<<Bv * (DI / SCH), 256>>>(deltabuf, xbbuf, dblbuf, xzbuf, Al, Dl, ybuf);
        gemm128<2><<<dim3(DM / 128, ML / 128), blk>>>(ybuf, ow, nullptr, hbuf, ML, DM, DI);
    }

    // out = h @ W2^T + b2     (N=128, K=256)
    gemm64<1, false><<<dim3(DIN / 64, ML / 128), blk>>>(hbuf, W2, b2, out, ML, DIN, DM);
}

// round 4
// speedup vs baseline: 3.8115x; 1.4457x over previous
#include <cuda_runtime.h>
#include <cuda_bf16.h>
#include <cstdint>

// ---------------- problem constants ----------------
#define Bv      4
#define Lv      2048
#define DIN     128
#define DM      256
#define NLAYERS 2
#define DI      512
#define DS      16
#define DCONV   4
#define DTR     16
#define ML      (Bv * Lv)          // 8192 rows
#define EPSV    1e-5f

// ---------------- scratch (static device memory; no allocs) ----------------
__device__ float g_h[ML * DM];           // residual stream
__device__ float g_u[ML * DM];           // rmsnorm output
__device__ float g_xz[ML * 2 * DI];      // in_proj output (x | z)
__device__ float g_xb[ML * DI];          // conv+silu output
__device__ float g_dbl[ML * 48];         // x_proj output (dt_rank | B | C)
__device__ float g_delta[ML * DI];       // softplus(dt)
__device__ float g_y[ML * DI];           // scan output (gated)

// ---------------- tf32 helpers ----------------------------------------------
__device__ __forceinline__ uint32_t f2tf(float x) {
    uint32_t r;
    asm("cvt.rna.tf32.f32 %0, %1;" : "=r"(r) : "f"(x));
    return r;
}

__device__ __forceinline__ void mma_tf32(float (&c)[4], const uint32_t (&a)[4],
                                         const uint32_t (&b)[2]) {
    asm volatile(
        "mma.sync.aligned.m16n8k8.row.col.f32.tf32.tf32.f32 "
        "{%0,%1,%2,%3}, {%4,%5,%6,%7}, {%8,%9}, {%0,%1,%2,%3};\n"
        : "+f"(c[0]), "+f"(c[1]), "+f"(c[2]), "+f"(c[3])
        : "r"(a[0]), "r"(a[1]), "r"(a[2]), "r"(a[3]), "r"(b[0]), "r"(b[1]));
}

// ============================================================================
// Tensor-core GEMM (tf32 mma.sync m16n8k8, fp32 accumulate).
// C[M,N] = A[M,K] @ W[N,K]^T.  MODE 0: C= ; 1: C=+bias ; 2: C+= .
// BM=128, BN in {128,64}, BK=16, 256 threads (8 warps), double-buffered smem.
// Requires M%128==0, K%16==0. NGUARD handles N not multiple of BN.
// ============================================================================
template <int MODE, int BN, bool NGUARD>
__global__ __launch_bounds__(256) void gemm_tc(
    const float* __restrict__ A, const float* __restrict__ W,
    const float* __restrict__ bias, float* __restrict__ C,
    int M, int N, int K)
{
    constexpr int BM = 128, BK = 16, BKP = BK + 4;
    constexpr int WCOLS = BN / 32;        // warps along n
    constexpr int WROWS = 8 / WCOLS;      // warps along m
    constexpr int WM = BM / WROWS;        // 64 (BN=128) or 32 (BN=64)
    constexpr int MI = WM / 16;           // 4 or 2
    constexpr int NI = 4;                 // 32 / 8

    __shared__ uint32_t As[2][BM][BKP];
    __shared__ uint32_t Ws[2][BN][BKP];

    const int bm = blockIdx.y * BM;
    const int bn = blockIdx.x * BN;
    const int tid  = threadIdx.x;
    const int warp = tid >> 5;
    const int lane = tid & 31;
    const int g = lane >> 2;              // group id 0..7
    const int q = lane & 3;               // thread in group 0..3

    const int wn = (warp % WCOLS) * 32;
    const int wm = (warp / WCOLS) * WM;

    // ---- global load mapping: float4 chunks ----
    constexpr int A_F4 = (BM * BK) / (256 * 4);   // 2
    constexpr int W_F4 = (BN * BK) / (256 * 4);   // 2 or 1
    const int lrow = tid >> 2;            // 0..63
    const int lf4  = (tid & 3) * 4;       // k offset 0,4,8,12

    float4 avr[A_F4], wvr[W_F4];

    auto LOAD_G = [&](int k0) {
#pragma unroll
        for (int i = 0; i < A_F4; i++) {
            const int r = lrow + i * 64;
            avr[i] = *(const float4*)&A[(size_t)(bm + r) * K + k0 + lf4];
        }
#pragma unroll
        for (int i = 0; i < W_F4; i++) {
            const int r = lrow + i * 64;
            if (!NGUARD || (bn + r) < N)
                wvr[i] = *(const float4*)&W[(size_t)(bn + r) * K + k0 + lf4];
            else
                wvr[i] = make_float4(0.f, 0.f, 0.f, 0.f);
        }
    };
    auto STORE_S = [&](int bf) {
#pragma unroll
        for (int i = 0; i < A_F4; i++) {
            const int r = lrow + i * 64;
            As[bf][r][lf4 + 0] = f2tf(avr[i].x);
            As[bf][r][lf4 + 1] = f2tf(avr[i].y);
            As[bf][r][lf4 + 2] = f2tf(avr[i].z);
            As[bf][r][lf4 + 3] = f2tf(avr[i].w);
        }
#pragma unroll
        for (int i = 0; i < W_F4; i++) {
            const int r = lrow + i * 64;
            Ws[bf][r][lf4 + 0] = f2tf(wvr[i].x);
            Ws[bf][r][lf4 + 1] = f2tf(wvr[i].y);
            Ws[bf][r][lf4 + 2] = f2tf(wvr[i].z);
            Ws[bf][r][lf4 + 3] = f2tf(wvr[i].w);
        }
    };

    float acc[MI][NI][4];
#pragma unroll
    for (int mi = 0; mi < MI; mi++)
#pragma unroll
        for (int ni = 0; ni < NI; ni++)
#pragma unroll
            for (int j = 0; j < 4; j++) acc[mi][ni][j] = 0.f;

    LOAD_G(0);
    STORE_S(0);
    __syncthreads();

    const int nkb = K / BK;
    int buf = 0;
    for (int kb = 0; kb < nkb; kb++) {
        if (kb + 1 < nkb) LOAD_G((kb + 1) * BK);

#pragma unroll
        for (int ks = 0; ks < 2; ks++) {      // two k=8 steps per buffer
            const int kk = ks * 8 + q;
            uint32_t a[MI][4];
#pragma unroll
            for (int mi = 0; mi < MI; mi++) {
                const int r = wm + mi * 16 + g;
                a[mi][0] = As[buf][r][kk];
                a[mi][1] = As[buf][r + 8][kk];
                a[mi][2] = As[buf][r][kk + 4];
                a[mi][3] = As[buf][r + 8][kk + 4];
            }
            uint32_t b[NI][2];
#pragma unroll
            for (int ni = 0; ni < NI; ni++) {
                const int r = wn + ni * 8 + g;
                b[ni][0] = Ws[buf][r][kk];
                b[ni][1] = Ws[buf][r][kk + 4];
            }
#pragma unroll
            for (int mi = 0; mi < MI; mi++)
#pragma unroll
                for (int ni = 0; ni < NI; ni++)
                    mma_tf32(acc[mi][ni], a[mi], b[ni]);
        }

        if (kb + 1 < nkb) STORE_S(buf ^ 1);
        __syncthreads();
        buf ^= 1;
    }

    // ---- epilogue ----
#pragma unroll
    for (int mi = 0; mi < MI; mi++) {
#pragma unroll
        for (int ni = 0; ni < NI; ni++) {
            const int col = bn + wn + ni * 8 + q * 2;
            if (NGUARD && col >= N) continue;
            const size_t r0 = bm + wm + mi * 16 + g;
            const size_t r1 = r0 + 8;
            float2 v0 = make_float2(acc[mi][ni][0], acc[mi][ni][1]);
            float2 v1 = make_float2(acc[mi][ni][2], acc[mi][ni][3]);
            if (MODE == 1) {
                float2 bb = *(const float2*)&bias[col];
                v0.x += bb.x; v0.y += bb.y;
                v1.x += bb.x; v1.y += bb.y;
            } else if (MODE == 2) {
                float2 o0 = *(const float2*)&C[r0 * N + col];
                float2 o1 = *(const float2*)&C[r1 * N + col];
                v0.x += o0.x; v0.y += o0.y;
                v1.x += o1.x; v1.y += o1.y;
            }
            *(float2*)&C[r0 * N + col] = v0;
            *(float2*)&C[r1 * N + col] = v1;
        }
    }
}

// ---------------- rmsnorm over last dim (DM=256), one block per row --------
__global__ __launch_bounds__(256) void rmsnorm_kernel(
    const float* __restrict__ h, const float* __restrict__ w,
    float* __restrict__ u)
{
    const size_t row = blockIdx.x;
    const int t = threadIdx.x;
    const float v = h[row * DM + t];
    float ss = v * v;
#pragma unroll
    for (int o = 16; o > 0; o >>= 1) ss += __shfl_xor_sync(0xffffffffu, ss, o);
    __shared__ float sred[8];
    if ((t & 31) == 0) sred[t >> 5] = ss;
    __syncthreads();
    float tot = 0.f;
#pragma unroll
    for (int i = 0; i < 8; i++) tot += sred[i];
    const float scale = rsqrtf(tot * (1.f / DM) + EPSV);
    u[row * DM + t] = v * scale * w[t];
}

// ---------------- causal depthwise conv (width 4) + silu -------------------
__global__ __launch_bounds__(256) void conv_silu_kernel(
    const float* __restrict__ xz, const float* __restrict__ cw,
    const float* __restrict__ cb, float* __restrict__ xb)
{
    const int i = blockIdx.x * blockDim.x + threadIdx.x;
    if (i >= ML * DI) return;
    const int e = i % DI;
    const int l = (i / DI) % Lv;
    const int b = i / (DI * Lv);
    float acc = cb[e];
#pragma unroll
    for (int j = 0; j < DCONV; j++) {
        const int ls = l - (DCONV - 1) + j;
        if (ls >= 0)
            acc = fmaf(xz[((size_t)(b * Lv + ls)) * (2 * DI) + e], cw[e * DCONV + j], acc);
    }
    const float s = acc / (1.f + __expf(-acc));
    xb[i] = s;
}

// ---------------- delta = softplus(dbl[:, :16] @ dt_w^T + dt_b) ------------
__global__ __launch_bounds__(512) void delta_kernel(
    const float* __restrict__ dbl, const float* __restrict__ dtw,
    const float* __restrict__ dtb, float* __restrict__ delta)
{
    const size_t row = blockIdx.x;
    const int e = threadIdx.x;
    __shared__ float s[DTR];
    if (e < DTR) s[e] = dbl[row * 48 + e];
    __syncthreads();
    float acc = dtb[e];
#pragma unroll
    for (int r = 0; r < DTR; r++) acc = fmaf(s[r], dtw[e * DTR + r], acc);
    const float sp = fmaxf(acc, 0.f) + log1pf(__expf(-fabsf(acc)));
    delta[row * DI + e] = sp;
}

// ============================================================================
// Selective scan: chunked double-buffered smem staging (R3 version).
// ============================================================================
#define SCH    16
#define CHUNK  64
#define NCHUNK (Lv / CHUNK)

__global__ __launch_bounds__(256) void scan_kernel(
    const float* __restrict__ delta, const float* __restrict__ u,
    const float* __restrict__ dbl,   const float* __restrict__ xz,
    const float* __restrict__ A_log, const float* __restrict__ Dp,
    float* __restrict__ y)
{
    __shared__ float s_dlt[2][CHUNK][SCH];
    __shared__ float s_uu [2][CHUNK][SCH];
    __shared__ float s_sz [2][CHUNK][SCH];
    __shared__ float s_B  [2][CHUNK][SCH];
    __shared__ float s_C  [2][CHUNK][SCH];

    const int tid  = threadIdx.x;
    const int warp = tid >> 5;
    const int lane = tid & 31;
    const int half = lane >> 4;
    const int n    = lane & 15;
    const int cl   = warp * 2 + half;
    const int b      = (int)(blockIdx.x >> 5);
    const int chbase = (blockIdx.x & 31) * SCH;
    const int ch     = chbase + cl;

    const float Aen = -__expf(A_log[ch * DS + n]);
    const float Dpe = Dp[ch];
    const size_t base = (size_t)b * Lv;

    const int rr = tid >> 4;
    const int cc = tid & 15;
    float r_d[4], r_u[4], r_z[4], r_b[4], r_c[4];

    auto LOADC = [&](int l0) {
#pragma unroll
        for (int i = 0; i < 4; i++) {
            const size_t row = base + l0 + rr + i * 16;
            r_d[i] = delta[row * DI + chbase + cc];
            r_u[i] = u[row * DI + chbase + cc];
            r_z[i] = xz[row * (size_t)(2 * DI) + DI + chbase + cc];
            r_b[i] = dbl[row * 48 + DTR + cc];
            r_c[i] = dbl[row * 48 + DTR + DS + cc];
        }
    };
    auto STORES = [&](int bf) {
#pragma unroll
        for (int i = 0; i < 4; i++) {
            const int t = rr + i * 16;
            s_dlt[bf][t][cc] = r_d[i];
            s_uu [bf][t][cc] = r_u[i];
            const float zz = r_z[i];
            s_sz [bf][t][cc] = zz / (1.f + __expf(-zz));
            s_B  [bf][t][cc] = r_b[i];
            s_C  [bf][t][cc] = r_c[i];
        }
    };

    LOADC(0);
    STORES(0);
    __syncthreads();

    float hst = 0.f;
    int buf = 0;
    for (int c = 0; c < NCHUNK; c++) {
        if (c + 1 < NCHUNK) LOADC((c + 1) * CHUNK);
        const int l0 = c * CHUNK;
#pragma unroll 4
        for (int t = 0; t < CHUNK; t++) {
            const float dlt = s_dlt[buf][t][cl];
            const float uu  = s_uu [buf][t][cl];
            const float Bn  = s_B  [buf][t][n];
            const float Cn  = s_C  [buf][t][n];
            const float dA  = __expf(dlt * Aen);
            hst = fmaf(dA, hst, dlt * uu * Bn);
            float acc = hst * Cn;
            acc += __shfl_xor_sync(0xffffffffu, acc, 1);
            acc += __shfl_xor_sync(0xffffffffu, acc, 2);
            acc += __shfl_xor_sync(0xffffffffu, acc, 4);
            acc += __shfl_xor_sync(0xffffffffu, acc, 8);
            if (n == 0) {
                y[(base + l0 + t) * DI + ch] = (acc + uu * Dpe) * s_sz[buf][t][cl];
            }
        }
        if (c + 1 < NCHUNK) STORES(buf ^ 1);
        __syncthreads();
        buf ^= 1;
    }
}

// ---------------- launch ----------------------------------------------------
extern "C" void kernel_launch(void* const* d_in, const int* in_sizes, int n_in,
                              void* d_out, int out_size)
{
    const float* x      = (const float*)d_in[0];
    const float* W1     = (const float*)d_in[1];
    const float* b1     = (const float*)d_in[2];
    const float* W2     = (const float*)d_in[3];
    const float* b2     = (const float*)d_in[4];
    const float* norm_w = (const float*)d_in[5];
    const float* in_w   = (const float*)d_in[6];
    const float* conv_w = (const float*)d_in[7];
    const float* conv_b = (const float*)d_in[8];
    const float* xp_w   = (const float*)d_in[9];
    const float* dt_w   = (const float*)d_in[10];
    const float* dt_b   = (const float*)d_in[11];
    const float* A_log  = (const float*)d_in[12];
    const float* D_par  = (const float*)d_in[13];
    const float* out_w  = (const float*)d_in[14];
    float* out = (float*)d_out;

    float *hbuf, *ubuf, *xzbuf, *xbbuf, *dblbuf, *deltabuf, *ybuf;
    cudaGetSymbolAddress((void**)&hbuf,     g_h);
    cudaGetSymbolAddress((void**)&ubuf,     g_u);
    cudaGetSymbolAddress((void**)&xzbuf,    g_xz);
    cudaGetSymbolAddress((void**)&xbbuf,    g_xb);
    cudaGetSymbolAddress((void**)&dblbuf,   g_dbl);
    cudaGetSymbolAddress((void**)&deltabuf, g_delta);
    cudaGetSymbolAddress((void**)&ybuf,     g_y);

    const dim3 blk(256);

    // h = x @ W1^T + b1       (M=8192, N=256, K=128)
    gemm_tc<1, 128, false><<<dim3(DM / 128, ML / 128), blk>>>(x, W1, b1, hbuf, ML, DM, DIN);

    for (int l = 0; l < NLAYERS; l++) {
        const float* nw  = norm_w + (size_t)l * DM;
        const float* iw  = in_w   + (size_t)l * 2 * DI * DM;
        const float* cw  = conv_w + (size_t)l * DI * DCONV;
        const float* cb  = conv_b + (size_t)l * DI;
        const float* xpw = xp_w   + (size_t)l * 48 * DI;
        const float* dtw = dt_w   + (size_t)l * DI * DTR;
        const float* dtb = dt_b   + (size_t)l * DI;
        const float* Al  = A_log  + (size_t)l * DI * DS;
        const float* Dl  = D_par  + (size_t)l * DI;
        const float* ow  = out_w  + (size_t)l * DM * DI;

        rmsnorm_kernel<<<ML, DM>>>(hbuf, nw, ubuf);
        // xz = u @ in_w^T      (N=1024, K=256)
        gemm_tc<0, 128, false><<<dim3(2 * DI / 128, ML / 128), blk>>>(ubuf, iw, nullptr, xzbuf, ML, 2 * DI, DM);
        conv_silu_kernel<<<(ML * DI + 255) / 256, blk>>>(xzbuf, cw, cb, xbbuf);
        // dbl = xb @ xp_w^T    (N=48, K=512)
        gemm_tc<0, 64, true><<<dim3(1, ML / 128), blk>>>(xbbuf, xpw, nullptr, dblbuf, ML, 48, DI);
        delta_kernel<<<ML, DI>>>(dblbuf, dtw, dtb, deltabuf);
        scan_kernel<<<Bv * (DI / SCH), 256>>>(deltabuf, xbbuf, dblbuf, xzbuf, Al, Dl, ybuf);
        // h += y @ out_w^T     (N=256, K=512)
        gemm_tc<2, 128, false><<<dim3(DM / 128, ML / 128), blk>>>(ybuf, ow, nullptr, hbuf, ML, DM, DI);
    }

    // out = h @ W2^T + b2     (N=128, K=256)
    gemm_tc<1, 128, false><<<dim3(1, ML / 128), blk>>>(hbuf, W2, b2, out, ML, DIN, DM);
}